// round 7
// baseline (speedup 1.0000x reference)
#include <cuda_runtime.h>

// Fused YOLO decode, single launch, smem-staged dataflow.
//
// Each block processes one tile of 169 cells (13*13, divides all HW) of one
// batch image:
//   Phase 1: stream the 45x169-float input tile gmem -> smem. All loads are
//            independent LDG.32 -> STS (structural MLP; coalesced; STS
//            stride 45 is bank-conflict-free).
//   Phase 2: decode 507 rows (169 cells x 3 anchors) from smem. smem is
//            cell-major (s[off*45+c]) so each row reads 15 consecutive
//            floats (conflict-free lane->bank permutation). Thread -> output
//            row directly: box rows written as 3 dense STG.64, mask dense.
// Output: boxes [N,6] in scale order 13,26,52, then mask [N].

#define TPB 256
#define TILE 169          // cells per block (13*13 divides 169/676/2704)
#define NCH 45
#define TFLOATS (NCH * TILE)   // 7605 floats per tile
#define TROWS (TILE * 3)       // 507 output rows per tile

#define BLK13 128         // 128 batches * (169/169)
#define BLK26 512         // 128 * (676/169)
#define BLK52 2048        // 128 * (2704/169)

#define ROWS13 64896
#define ROWS26 259584
#define ROWS52 1038336
#define ROWBASE13 0
#define ROWBASE26 ROWS13
#define ROWBASE52 (ROWS13 + ROWS26)

template<int W, int TILES_PER_B, int STRIDE>
__device__ __forceinline__ void decode_tile(const float* __restrict__ in,
                                            const float* __restrict__ anchors,
                                            float thr,
                                            float* __restrict__ boxes,
                                            float* __restrict__ mask,
                                            size_t rowbase,
                                            int blk, int t,
                                            float* __restrict__ s)
{
    constexpr int HW = W * W;
    const int b  = blk / TILES_PER_B;
    const int j  = blk - b * TILES_PER_B;
    const int t0 = j * TILE;

    const float* src = in + (size_t)b * NCH * HW + t0;

    // ---- Phase 1: gmem -> smem (independent scalar loads, cell-major smem)
    for (int r = t; r < TFLOATS; r += TPB) {
        const int c   = r / TILE;          // compile-time-const divisor
        const int off = r - c * TILE;
        s[off * NCH + c] = __ldg(src + (size_t)c * HW + off);
    }
    __syncthreads();

    // ---- Phase 2: decode. Row r -> (cell lc = r/3, anchor a = r%3).
    for (int r = t; r < TROWS; r += TPB) {
        const int lc = r / 3;
        const int a  = r - lc * 3;

        const float* sc = s + lc * NCH + a * 15;   // 15 consecutive floats

        const float o0 = sc[0];
        const float o1 = sc[1];
        const float o2 = sc[2];
        const float o3 = sc[3];
        const float o4 = sc[4];

        float best = sc[5];
        int bi = 0;
        #pragma unroll
        for (int c = 1; c < 10; ++c) {
            const float q = sc[5 + c];
            if (q > best) { best = q; bi = c; }
        }

        const int cw = t0 + lc;
        const int h  = cw / W;                 // compile-time W
        const int w  = cw - h * W;

        const float px = ((float)w + o1) * (float)STRIDE;
        const float py = ((float)h + o2) * (float)STRIDE;
        const float pw = __ldg(anchors + 2 * a + 0) * __expf(o3);
        const float ph = __ldg(anchors + 2 * a + 1) * __expf(o4);

        const size_t orow = rowbase + ((size_t)b * HW + t0) * 3 + r;
        float2* ob = (float2*)(boxes + orow * 6);
        ob[0] = make_float2(o0,              px - 0.5f * pw);
        ob[1] = make_float2(py - 0.5f * ph,  px + 0.5f * pw);
        ob[2] = make_float2(py + 0.5f * ph,  (float)bi);

        mask[orow] = (o0 > thr) ? 1.0f : 0.0f;
    }
}

__global__ __launch_bounds__(TPB)
void decode_fused_kernel(const float* __restrict__ in13,
                         const float* __restrict__ in26,
                         const float* __restrict__ in52,
                         const float* __restrict__ anc13,
                         const float* __restrict__ anc26,
                         const float* __restrict__ anc52,
                         const float* __restrict__ thresh_p,
                         float* __restrict__ boxes,
                         float* __restrict__ mask)
{
    __shared__ float s[TFLOATS];   // 30,420 B

    const int bid = blockIdx.x;
    const int t = threadIdx.x;
    const float thr = __ldg(thresh_p);

    if (bid < BLK52) {
        decode_tile<52, 16, 8>(in52, anc52, thr, boxes, mask,
                               (size_t)ROWBASE52, bid, t, s);
    } else if (bid < BLK52 + BLK26) {
        decode_tile<26, 4, 16>(in26, anc26, thr, boxes, mask,
                               (size_t)ROWBASE26, bid - BLK52, t, s);
    } else {
        decode_tile<13, 1, 32>(in13, anc13, thr, boxes, mask,
                               (size_t)ROWBASE13, bid - (BLK52 + BLK26), t, s);
    }
}

extern "C" void kernel_launch(void* const* d_in, const int* in_sizes, int n_in,
                              void* d_out, int out_size)
{
    const float* out13 = (const float*)d_in[0];
    const float* out26 = (const float*)d_in[1];
    const float* out52 = (const float*)d_in[2];
    const float* anc13 = (const float*)d_in[3];
    const float* anc26 = (const float*)d_in[4];
    const float* anc52 = (const float*)d_in[5];
    const float* thr   = (const float*)d_in[6];

    float* out = (float*)d_out;
    const int rowsTot = ROWS13 + ROWS26 + ROWS52;   // 1,362,816

    float* boxes = out;                       // [rowsTot, 6]
    float* mask  = out + (size_t)rowsTot * 6; // [rowsTot]

    decode_fused_kernel<<<BLK52 + BLK26 + BLK13, TPB>>>(
        out13, out26, out52, anc13, anc26, anc52, thr, boxes, mask);
}

// round 9
// speedup vs baseline: 1.7293x; 1.7293x over previous
#include <cuda_runtime.h>
#include <cuda_pipeline.h>
#include <cstdint>

// Fused YOLO decode, single launch, cp.async-staged dataflow.
//
// Each block handles one tile of 169 cells (13*13 divides every HW) of one
// image:
//   Phase 1: 30 fully-unrolled independent 4-byte cp.async per thread copy
//            the 45x169-float tile gmem -> smem (cell-major, pitch 45).
//            LDGSTS has no destination register -> ptxas cannot serialize
//            the batch; structural MLP covers DRAM latency.
//   Phase 2: decode 507 rows (169 cells x 3 anchors) from smem. Each row
//            reads 15 consecutive smem floats (conflict-free permutation),
//            writes 3 dense STG.64 + 1 mask float, thread->row direct.
// Output: boxes [N,6] in scale order 13,26,52, then mask [N].

#define TPB 256
#define TILE 169
#define NCH 45
#define TFLOATS (NCH * TILE)   // 7605
#define TROWS   (TILE * 3)     // 507
#define NCOPY   30             // ceil(7605/256)

#define BLK13 128
#define BLK26 512
#define BLK52 2048

#define ROWS13 64896
#define ROWS26 259584
#define ROWS52 1038336
#define ROWBASE13 0
#define ROWBASE26 ROWS13
#define ROWBASE52 (ROWS13 + ROWS26)

template<int W, int TILES_PER_B, int STRIDE>
__device__ __forceinline__ void decode_tile(const float* __restrict__ in,
                                            const float* __restrict__ anchors,
                                            float thr,
                                            float* __restrict__ boxes,
                                            float* __restrict__ mask,
                                            size_t rowbase,
                                            int blk, int t,
                                            float* __restrict__ s)
{
    constexpr int HW = W * W;
    const int b  = blk / TILES_PER_B;
    const int j  = blk - b * TILES_PER_B;
    const int t0 = j * TILE;

    const float* src = in + (size_t)b * NCH * HW + t0;

    // ---- Phase 1: gmem -> smem via independent 4B cp.async (LDGSTS) ----
    // r = c*TILE + off ; gmem addr = src + c*HW + off ; smem = s[off*NCH+c]
    #pragma unroll
    for (int k = 0; k < NCOPY; ++k) {
        const int r = t + k * TPB;
        if (k == NCOPY - 1 && r >= TFLOATS) break;
        const int c   = r / TILE;            // compile-time divisor
        const int off = r - c * TILE;
        __pipeline_memcpy_async(&s[off * NCH + c],
                                src + (size_t)c * HW + off, 4);
    }
    __pipeline_commit();
    __pipeline_wait_prior(0);
    __syncthreads();

    // ---- Phase 2: decode. Row r -> (cell lc = r/3, anchor a = r%3) ----
    #pragma unroll
    for (int it = 0; it < 2; ++it) {
        const int r = t + it * TPB;
        if (it == 1 && r >= TROWS) break;

        const int lc = r / 3;
        const int a  = r - 3 * lc;

        const float* sc = s + lc * NCH + a * 15;   // 15 consecutive floats

        const float o0 = sc[0];
        const float o1 = sc[1];
        const float o2 = sc[2];
        const float o3 = sc[3];
        const float o4 = sc[4];

        float best = sc[5];
        int bi = 0;
        #pragma unroll
        for (int c = 1; c < 10; ++c) {
            const float q = sc[5 + c];
            if (q > best) { best = q; bi = c; }
        }

        const int cw = t0 + lc;
        const int h  = cw / W;                 // compile-time W
        const int w  = cw - h * W;

        const float px = ((float)w + o1) * (float)STRIDE;
        const float py = ((float)h + o2) * (float)STRIDE;
        const float pw = __ldg(anchors + 2 * a + 0) * __expf(o3);
        const float ph = __ldg(anchors + 2 * a + 1) * __expf(o4);

        const size_t orow = rowbase + ((size_t)b * HW + t0) * 3 + r;
        float2* ob = (float2*)(boxes + orow * 6);
        ob[0] = make_float2(o0,              px - 0.5f * pw);
        ob[1] = make_float2(py - 0.5f * ph,  px + 0.5f * pw);
        ob[2] = make_float2(py + 0.5f * ph,  (float)bi);

        mask[orow] = (o0 > thr) ? 1.0f : 0.0f;
    }
}

__global__ __launch_bounds__(TPB)
void decode_fused_kernel(const float* __restrict__ in13,
                         const float* __restrict__ in26,
                         const float* __restrict__ in52,
                         const float* __restrict__ anc13,
                         const float* __restrict__ anc26,
                         const float* __restrict__ anc52,
                         const float* __restrict__ thresh_p,
                         float* __restrict__ boxes,
                         float* __restrict__ mask)
{
    __shared__ float s[TFLOATS];   // 30,420 B

    const int bid = blockIdx.x;
    const int t = threadIdx.x;
    const float thr = __ldg(thresh_p);

    if (bid < BLK52) {
        decode_tile<52, 16, 8>(in52, anc52, thr, boxes, mask,
                               (size_t)ROWBASE52, bid, t, s);
    } else if (bid < BLK52 + BLK26) {
        decode_tile<26, 4, 16>(in26, anc26, thr, boxes, mask,
                               (size_t)ROWBASE26, bid - BLK52, t, s);
    } else {
        decode_tile<13, 1, 32>(in13, anc13, thr, boxes, mask,
                               (size_t)ROWBASE13, bid - (BLK52 + BLK26), t, s);
    }
}

extern "C" void kernel_launch(void* const* d_in, const int* in_sizes, int n_in,
                              void* d_out, int out_size)
{
    const float* out13 = (const float*)d_in[0];
    const float* out26 = (const float*)d_in[1];
    const float* out52 = (const float*)d_in[2];
    const float* anc13 = (const float*)d_in[3];
    const float* anc26 = (const float*)d_in[4];
    const float* anc52 = (const float*)d_in[5];
    const float* thr   = (const float*)d_in[6];

    float* out = (float*)d_out;
    const int rowsTot = ROWS13 + ROWS26 + ROWS52;   // 1,362,816

    float* boxes = out;                       // [rowsTot, 6]
    float* mask  = out + (size_t)rowsTot * 6; // [rowsTot]

    decode_fused_kernel<<<BLK52 + BLK26 + BLK13, TPB>>>(
        out13, out26, out52, anc13, anc26, anc52, thr, boxes, mask);
}

// round 10
// speedup vs baseline: 2.2693x; 1.3123x over previous
#include <cuda_runtime.h>
#include <cuda_pipeline.h>
#include <cstdint>

// Fused YOLO decode, single launch, 16B-cp.async-staged dataflow.
//
// Each block handles one tile of 169 cells of one image.
//   Phase 1 (scales 52/26): all 45 channel rows of the tile share one
//     misalignment m = (j*169) mod 4, so copy the aligned superset
//     [t0-m, t0-m+172) of each row as 43 LDGSTS.128 -> smem pitch 172.
//     Scale 13: whole image is contiguous (7605 floats); aligned superset
//     copy of 1902 float4, m = b mod 4.
//   Phase 2: decode 507 rows from smem (channel-major, stride PITCH);
//     3 dense STG.64 + 1 mask float per row, thread->row direct.
// Output: boxes [N,6] in scale order 13,26,52, then mask [N].

#define TPB 256
#define TILE 169
#define NCH 45
#define TROWS (TILE * 3)       // 507

#define PITCH_V 172            // smem floats per channel row (43 float4)
#define NF4_V  (NCH * 43)      // 1935 float4 per tile (scales 26/52)
#define NF4_13 1902            // ceil... (45*169 + 3)/4 = 7608/4

#define SMEM_FLOATS (NCH * PITCH_V)   // 7740 >= 7608 (scale-13 use)

#define BLK13 128
#define BLK26 512
#define BLK52 2048

#define ROWS13 64896
#define ROWS26 259584
#define ROWS52 1038336
#define ROWBASE13 0
#define ROWBASE26 ROWS13
#define ROWBASE52 (ROWS13 + ROWS26)

// ---- decode 507 rows from smem; channel c, cell lc at s[c*PITCH + m + lc]
template<int W, int STRIDE, int PITCH>
__device__ __forceinline__ void decode_tile(const float* __restrict__ s,
                                            int m,
                                            const float* __restrict__ anchors,
                                            float thr,
                                            float* __restrict__ boxes,
                                            float* __restrict__ mask,
                                            size_t orow0, int t0, int t)
{
    #pragma unroll
    for (int it = 0; it < 2; ++it) {
        const int r = t + it * TPB;
        if (it == 1 && r >= TROWS) break;

        const int lc = r / 3;
        const int a  = r - 3 * lc;

        const float* sc = s + (a * 15) * PITCH + m + lc;

        const float o0 = sc[0 * PITCH];
        const float o1 = sc[1 * PITCH];
        const float o2 = sc[2 * PITCH];
        const float o3 = sc[3 * PITCH];
        const float o4 = sc[4 * PITCH];

        float best = sc[5 * PITCH];
        int bi = 0;
        #pragma unroll
        for (int c = 1; c < 10; ++c) {
            const float q = sc[(5 + c) * PITCH];
            if (q > best) { best = q; bi = c; }
        }

        const int cw = t0 + lc;
        const int h  = cw / W;                 // compile-time W
        const int w  = cw - h * W;

        const float px = ((float)w + o1) * (float)STRIDE;
        const float py = ((float)h + o2) * (float)STRIDE;
        const float pw = __ldg(anchors + 2 * a + 0) * __expf(o3);
        const float ph = __ldg(anchors + 2 * a + 1) * __expf(o4);

        const size_t orow = orow0 + r;
        float2* ob = (float2*)(boxes + orow * 6);
        ob[0] = make_float2(o0,              px - 0.5f * pw);
        ob[1] = make_float2(py - 0.5f * ph,  px + 0.5f * pw);
        ob[2] = make_float2(py + 0.5f * ph,  (float)bi);

        mask[orow] = (o0 > thr) ? 1.0f : 0.0f;
    }
}

// ---- scales 52/26: strided-row tile, 16B copy with alignment shift ----
template<int W, int TILES_PER_B, int STRIDE>
__device__ __forceinline__ void tile_path(const float* __restrict__ in,
                                          const float* __restrict__ anchors,
                                          float thr,
                                          float* __restrict__ boxes,
                                          float* __restrict__ mask,
                                          size_t rowbase,
                                          int blk, int t,
                                          float4* __restrict__ s4)
{
    constexpr int HW  = W * W;        // % 4 == 0
    constexpr int HW4 = HW / 4;
    const int b  = blk / TILES_PER_B;
    const int j  = blk - b * TILES_PER_B;
    const int t0 = j * TILE;
    const int m  = t0 & 3;            // base b*45*HW is 0 mod 4

    const float4* src4 = (const float4*)(in) + ((size_t)b * NCH * HW + t0 - m) / 4;

    // 1935 float4: row c (43 f4) -> smem f4 index c*43+q
    #pragma unroll
    for (int k = 0; k < 8; ++k) {
        const int r = t + k * TPB;
        if (k == 7 && r >= NF4_V) break;
        const int c = r / 43;
        const int q = r - c * 43;
        __pipeline_memcpy_async(&s4[c * 43 + q], src4 + c * HW4 + q, 16);
    }
    __pipeline_commit();
    __pipeline_wait_prior(0);
    __syncthreads();

    const size_t orow0 = rowbase + ((size_t)b * HW + t0) * 3;
    decode_tile<W, STRIDE, PITCH_V>((const float*)s4, m, anchors, thr,
                                    boxes, mask, orow0, t0, t);
}

__global__ __launch_bounds__(TPB)
void decode_fused_kernel(const float* __restrict__ in13,
                         const float* __restrict__ in26,
                         const float* __restrict__ in52,
                         const float* __restrict__ anc13,
                         const float* __restrict__ anc26,
                         const float* __restrict__ anc52,
                         const float* __restrict__ thresh_p,
                         float* __restrict__ boxes,
                         float* __restrict__ mask)
{
    __shared__ alignas(16) float s[SMEM_FLOATS];   // 30,960 B
    float4* s4 = (float4*)s;

    const int bid = blockIdx.x;
    const int t = threadIdx.x;
    const float thr = __ldg(thresh_p);

    if (bid < BLK52) {
        tile_path<52, 16, 8>(in52, anc52, thr, boxes, mask,
                             (size_t)ROWBASE52, bid, t, s4);
    } else if (bid < BLK52 + BLK26) {
        tile_path<26, 4, 16>(in26, anc26, thr, boxes, mask,
                             (size_t)ROWBASE26, bid - BLK52, t, s4);
    } else {
        // ---- scale 13: contiguous image, aligned superset copy ----
        const int b = bid - (BLK52 + BLK26);
        const int m = (b * (NCH * TILE)) & 3;          // 7605 % 4 == 1 -> b&3
        const float4* src4 = (const float4*)(in13)
                           + ((size_t)b * NCH * TILE - m) / 4;

        #pragma unroll
        for (int k = 0; k < 8; ++k) {
            const int r = t + k * TPB;
            if (k == 7 && r >= NF4_13) break;
            __pipeline_memcpy_async(&s4[r], src4 + r, 16);
        }
        __pipeline_commit();
        __pipeline_wait_prior(0);
        __syncthreads();

        const size_t orow0 = (size_t)ROWBASE13 + (size_t)b * TROWS;
        decode_tile<13, 32, TILE>(s, m, anc13, thr, boxes, mask, orow0, 0, t);
    }
}

extern "C" void kernel_launch(void* const* d_in, const int* in_sizes, int n_in,
                              void* d_out, int out_size)
{
    const float* out13 = (const float*)d_in[0];
    const float* out26 = (const float*)d_in[1];
    const float* out52 = (const float*)d_in[2];
    const float* anc13 = (const float*)d_in[3];
    const float* anc26 = (const float*)d_in[4];
    const float* anc52 = (const float*)d_in[5];
    const float* thr   = (const float*)d_in[6];

    float* out = (float*)d_out;
    const int rowsTot = ROWS13 + ROWS26 + ROWS52;   // 1,362,816

    float* boxes = out;                       // [rowsTot, 6]
    float* mask  = out + (size_t)rowsTot * 6; // [rowsTot]

    decode_fused_kernel<<<BLK52 + BLK26 + BLK13, TPB>>>(
        out13, out26, out52, anc13, anc26, anc52, thr, boxes, mask);
}

// round 11
// speedup vs baseline: 2.2895x; 1.0089x over previous
#include <cuda_runtime.h>
#include <cuda_pipeline.h>
#include <cstdint>

// Fused YOLO decode, single launch, cp.async-staged, smem-staged stores.
//
// Block = 512 threads, one 169-cell tile (13*13 divides every HW):
//   Phase 1: 16B cp.async copy of the 45-channel tile into smem
//            (channel-major, pitch 172 floats; per-tile alignment shift m).
//   Phase 2: single-pass decode: thread t -> row t (507 rows), results held
//            in registers; mask written directly (dense).
//   Phase 3: input tile is dead -> stage the 507x6 box floats IN PLACE in
//            the same smem buffer, then copy out as dense float2 (every
//            global store instruction is warp-contiguous).
// Output: boxes [N,6] in scale order 13,26,52, then mask [N].

#define TPB 512
#define TILE 169
#define NCH 45
#define TROWS (TILE * 3)        // 507
#define NSTG  (TROWS * 3)       // 1521 float2 of box data

#define PITCH_V 172             // 43 float4 per channel row
#define NF4_V  (NCH * 43)       // 1935
#define NF4_13 1902             // (45*169 + 3)/4

#define SMEM_FLOATS (NCH * PITCH_V)   // 7740 floats = 30960 B

#define BLK13 128
#define BLK26 512
#define BLK52 2048

#define ROWS13 64896
#define ROWS26 259584
#define ROWS52 1038336
#define ROWBASE13 0
#define ROWBASE26 ROWS13
#define ROWBASE52 (ROWS13 + ROWS26)

// decode 507 rows (single pass) + in-place stage + dense copy-out
template<int W, int STRIDE, int PITCH>
__device__ __forceinline__ void decode_tile(float* s, int m,
                                            const float* __restrict__ anchors,
                                            float thr,
                                            float* __restrict__ boxes,
                                            float* __restrict__ mask,
                                            size_t orow0, int t0, int t)
{
    float o0, x1, y1, x2, y2, kind;
    const bool active = (t < TROWS);

    if (active) {
        const int lc = t / 3;
        const int a  = t - 3 * lc;

        const float* sc = s + (a * 15) * PITCH + m + lc;

        o0 = sc[0 * PITCH];
        const float d1 = sc[1 * PITCH];
        const float d2 = sc[2 * PITCH];
        const float d3 = sc[3 * PITCH];
        const float d4 = sc[4 * PITCH];

        float best = sc[5 * PITCH];
        int bi = 0;
        #pragma unroll
        for (int c = 1; c < 10; ++c) {
            const float q = sc[(5 + c) * PITCH];
            if (q > best) { best = q; bi = c; }
        }

        const int cw = t0 + lc;
        const int h  = cw / W;                 // compile-time W
        const int w  = cw - h * W;

        const float px = ((float)w + d1) * (float)STRIDE;
        const float py = ((float)h + d2) * (float)STRIDE;
        const float pw = __ldg(anchors + 2 * a + 0) * __expf(d3);
        const float ph = __ldg(anchors + 2 * a + 1) * __expf(d4);

        x1 = px - 0.5f * pw;  y1 = py - 0.5f * ph;
        x2 = px + 0.5f * pw;  y2 = py + 0.5f * ph;
        kind = (float)bi;

        mask[orow0 + t] = (o0 > thr) ? 1.0f : 0.0f;
    }

    __syncthreads();                  // all input reads complete

    if (active) {                     // stage rows in place (input is dead)
        float2* st = (float2*)s;
        st[t * 3 + 0] = make_float2(o0, x1);
        st[t * 3 + 1] = make_float2(y1, x2);
        st[t * 3 + 2] = make_float2(y2, kind);
    }

    __syncthreads();

    // dense copy-out: 1521 float2, warp-contiguous stores (8B-aligned dest)
    float2* dst = (float2*)(boxes + orow0 * 6);
    const float2* st = (const float2*)s;
    #pragma unroll
    for (int k = 0; k < 3; ++k) {
        const int idx = t + k * TPB;
        if (idx < NSTG) dst[idx] = st[idx];
    }
}

template<int W, int TILES_PER_B, int STRIDE>
__device__ __forceinline__ void tile_path(const float* __restrict__ in,
                                          const float* __restrict__ anchors,
                                          float thr,
                                          float* __restrict__ boxes,
                                          float* __restrict__ mask,
                                          size_t rowbase,
                                          int blk, int t, float* s)
{
    constexpr int HW  = W * W;        // % 4 == 0
    constexpr int HW4 = HW / 4;
    const int b  = blk / TILES_PER_B;
    const int j  = blk - b * TILES_PER_B;
    const int t0 = j * TILE;
    const int m  = t0 & 3;

    float4* s4 = (float4*)s;
    const float4* src4 = (const float4*)(in) + ((size_t)b * NCH * HW + t0 - m) / 4;

    #pragma unroll
    for (int k = 0; k < 4; ++k) {
        const int r = t + k * TPB;
        if (k == 3 && r >= NF4_V) break;
        const int c = r / 43;
        const int q = r - c * 43;
        __pipeline_memcpy_async(&s4[c * 43 + q], src4 + c * HW4 + q, 16);
    }
    __pipeline_commit();
    __pipeline_wait_prior(0);
    __syncthreads();

    const size_t orow0 = rowbase + ((size_t)b * HW + t0) * 3;
    decode_tile<W, STRIDE, PITCH_V>(s, m, anchors, thr, boxes, mask, orow0, t0, t);
}

__global__ __launch_bounds__(TPB, 3)
void decode_fused_kernel(const float* __restrict__ in13,
                         const float* __restrict__ in26,
                         const float* __restrict__ in52,
                         const float* __restrict__ anc13,
                         const float* __restrict__ anc26,
                         const float* __restrict__ anc52,
                         const float* __restrict__ thresh_p,
                         float* __restrict__ boxes,
                         float* __restrict__ mask)
{
    __shared__ alignas(16) float s[SMEM_FLOATS];   // 30,960 B

    const int bid = blockIdx.x;
    const int t = threadIdx.x;
    const float thr = __ldg(thresh_p);

    if (bid < BLK52) {
        tile_path<52, 16, 8>(in52, anc52, thr, boxes, mask,
                             (size_t)ROWBASE52, bid, t, s);
    } else if (bid < BLK52 + BLK26) {
        tile_path<26, 4, 16>(in26, anc26, thr, boxes, mask,
                             (size_t)ROWBASE26, bid - BLK52, t, s);
    } else {
        // ---- scale 13: contiguous image, aligned superset copy ----
        const int b = bid - (BLK52 + BLK26);
        const int m = b & 3;                       // 7605 % 4 == 1
        float4* s4 = (float4*)s;
        const float4* src4 = (const float4*)(in13)
                           + ((size_t)b * (NCH * TILE) - m) / 4;

        #pragma unroll
        for (int k = 0; k < 4; ++k) {
            const int r = t + k * TPB;
            if (k == 3 && r >= NF4_13) break;
            __pipeline_memcpy_async(&s4[r], src4 + r, 16);
        }
        __pipeline_commit();
        __pipeline_wait_prior(0);
        __syncthreads();

        const size_t orow0 = (size_t)ROWBASE13 + (size_t)b * TROWS;
        decode_tile<13, 32, TILE>(s, m, anc13, thr, boxes, mask, orow0, 0, t);
    }
}

extern "C" void kernel_launch(void* const* d_in, const int* in_sizes, int n_in,
                              void* d_out, int out_size)
{
    const float* out13 = (const float*)d_in[0];
    const float* out26 = (const float*)d_in[1];
    const float* out52 = (const float*)d_in[2];
    const float* anc13 = (const float*)d_in[3];
    const float* anc26 = (const float*)d_in[4];
    const float* anc52 = (const float*)d_in[5];
    const float* thr   = (const float*)d_in[6];

    float* out = (float*)d_out;
    const int rowsTot = ROWS13 + ROWS26 + ROWS52;   // 1,362,816

    float* boxes = out;                       // [rowsTot, 6]
    float* mask  = out + (size_t)rowsTot * 6; // [rowsTot]

    decode_fused_kernel<<<BLK52 + BLK26 + BLK13, TPB>>>(
        out13, out26, out52, anc13, anc26, anc52, thr, boxes, mask);
}